// round 15
// baseline (speedup 1.0000x reference)
#include <cuda_runtime.h>
#include <cuda_bf16.h>
#include <math.h>
#include <stdint.h>

// Problem constants
#define NN   8192
#define DIN  256
#define HID  512
#define CAP  128   // max stored in-edges per column (avg 32, max ~60 statistically)

// ---------------- device scratch (no runtime allocation allowed) -------------
__device__ int   gx_cnt[NN];
__device__ int   gx_ell[NN * CAP];
__device__ float gx_dis[NN];
__device__ float gx_p1[NN * DIN];          // propagate(x) fp32
__device__ float gx_h [NN * HID];          // relu(layer1) fp32
__device__ float gx_t [NN * DIN];          // h @ W2 fp32 (pre-propagate)
__device__ __nv_bfloat16 gx_w1h[HID * DIN], gx_w1l[HID * DIN]; // W1^T: [n<512][k<256]
__device__ __nv_bfloat16 gx_w2h[DIN * HID], gx_w2l[DIN * HID]; // W2^T: [n<256][k<512]

// ---------------------------------------------------------------------------
__global__ void kx_zero_cnt() {
    int i = blockIdx.x * blockDim.x + threadIdx.x;
    if (i < NN) gx_cnt[i] = 0;
}

// Scan dense A (row-major [i][j]) as float4, push nonzeros into per-column ELL.
__global__ void kx_extract(const float4* __restrict__ A4) {
    const int total = NN * NN / 4;  // 16777216
    for (int idx = blockIdx.x * blockDim.x + threadIdx.x; idx < total;
         idx += gridDim.x * blockDim.x) {
        float4 v = A4[idx];
        if (v.x == 0.f && v.y == 0.f && v.z == 0.f && v.w == 0.f) continue;
        int base = idx << 2;
        int i = base >> 13;        // row
        int j = base & (NN - 1);   // col
        if (v.x != 0.f) { int s = atomicAdd(&gx_cnt[j],     1); if (s < CAP) gx_ell[(j    ) * CAP + s] = i; }
        if (v.y != 0.f) { int s = atomicAdd(&gx_cnt[j + 1], 1); if (s < CAP) gx_ell[(j + 1) * CAP + s] = i; }
        if (v.z != 0.f) { int s = atomicAdd(&gx_cnt[j + 2], 1); if (s < CAP) gx_ell[(j + 2) * CAP + s] = i; }
        if (v.w != 0.f) { int s = atomicAdd(&gx_cnt[j + 3], 1); if (s < CAP) gx_ell[(j + 3) * CAP + s] = i; }
    }
}

__global__ void kx_dis() {
    int j = blockIdx.x * blockDim.x + threadIdx.x;
    if (j < NN) {
        float deg = (float)gx_cnt[j] + 1.0f;   // self loop
        gx_dis[j] = rsqrtf(deg);
    }
}

// ----------------- split helpers (fp32 -> bf16 hi + bf16 lo) -----------------
__device__ __forceinline__ void split_one(float v, __nv_bfloat16* hi, __nv_bfloat16* lo) {
    __nv_bfloat16 h = __float2bfloat16(v);
    *hi = h;
    *lo = __float2bfloat16(v - __bfloat162float(h));
}

// Transpose + split weights: W [K][Nc] row-major -> th/tl [n*K + k].
// Thread owns (n, k-pair): strided 4B reads, fully coalesced packed stores.
__device__ __forceinline__ void tsplit_fast(const float* __restrict__ W,
                                            __nv_bfloat16* __restrict__ th,
                                            __nv_bfloat16* __restrict__ tl,
                                            int K, int Nc) {
    int kh = K >> 1;                   // k-pairs per column
    int tot = Nc * kh;
    for (int idx = blockIdx.x * blockDim.x + threadIdx.x; idx < tot;
         idx += gridDim.x * blockDim.x) {
        int n = idx / kh;
        int k = (idx - n * kh) << 1;
        float v0 = W[(size_t)k * Nc + n];
        float v1 = W[(size_t)(k + 1) * Nc + n];
        __nv_bfloat16 h0, l0, h1, l1;
        split_one(v0, &h0, &l0);
        split_one(v1, &h1, &l1);
        __nv_bfloat162 hp, lp;
        hp.x = h0; hp.y = h1;
        lp.x = l0; lp.y = l1;
        size_t o = (size_t)n * K + k;  // 4B-aligned (k even)
        *(__nv_bfloat162*)(th + o) = hp;
        *(__nv_bfloat162*)(tl + o) = lp;
    }
}
__global__ void kx_tsplit_w1(const float* __restrict__ W1) { tsplit_fast(W1, gx_w1h, gx_w1l, DIN, HID); }
__global__ void kx_tsplit_w2(const float* __restrict__ W2) { tsplit_fast(W2, gx_w2h, gx_w2l, HID, DIN); }

// ----------------- sparse propagate (layer 1, fp32 out; proven) --------------
__global__ void kx_prop1(const float* __restrict__ x) {
    __shared__ int   s_idx[CAP];
    __shared__ float s_w[CAP];
    int j = blockIdx.x;
    int t = threadIdx.x;           // d = DIN
    int cnt = gx_cnt[j];
    if (cnt > CAP) cnt = CAP;
    if (t < cnt) {
        int i = gx_ell[j * CAP + t];
        s_idx[t] = i;
        s_w[t]   = gx_dis[i];
    }
    __syncthreads();
    float a0 = 0.f, a1 = 0.f, a2 = 0.f, a3 = 0.f;
    int e = 0;
    for (; e + 4 <= cnt; e += 4) {
        a0 += s_w[e]     * x[(size_t)s_idx[e]     * DIN + t];
        a1 += s_w[e + 1] * x[(size_t)s_idx[e + 1] * DIN + t];
        a2 += s_w[e + 2] * x[(size_t)s_idx[e + 2] * DIN + t];
        a3 += s_w[e + 3] * x[(size_t)s_idx[e + 3] * DIN + t];
    }
    for (; e < cnt; e++)
        a0 += s_w[e] * x[(size_t)s_idx[e] * DIN + t];
    float acc = (a0 + a1) + (a2 + a3);
    float dj = gx_dis[j];
    gx_p1[(size_t)j * DIN + t] = dj * acc + dj * dj * x[(size_t)j * DIN + t];
}

// ----------------- layer-2 propagate + full epilogue (d = 256) ---------------
// out[j,t] = sigmoid(sp * (dj*sum_i dis_i*t_i + dj^2*t_j + b2[t] + x[j,t]))
__global__ void kx_prop2epi(const float* __restrict__ x,
                            const float* __restrict__ b2,
                            const float* __restrict__ sigp,
                            float* __restrict__ out) {
    __shared__ int   s_idx[CAP];
    __shared__ float s_w[CAP];
    int j = blockIdx.x;
    int t = threadIdx.x;           // d = DIN
    int cnt = gx_cnt[j];
    if (cnt > CAP) cnt = CAP;
    if (t < cnt) {
        int i = gx_ell[j * CAP + t];
        s_idx[t] = i;
        s_w[t]   = gx_dis[i];
    }
    __syncthreads();
    float a0 = 0.f, a1 = 0.f, a2 = 0.f, a3 = 0.f;
    int e = 0;
    for (; e + 4 <= cnt; e += 4) {
        a0 += s_w[e]     * gx_t[(size_t)s_idx[e]     * DIN + t];
        a1 += s_w[e + 1] * gx_t[(size_t)s_idx[e + 1] * DIN + t];
        a2 += s_w[e + 2] * gx_t[(size_t)s_idx[e + 2] * DIN + t];
        a3 += s_w[e + 3] * gx_t[(size_t)s_idx[e + 3] * DIN + t];
    }
    for (; e < cnt; e++)
        a0 += s_w[e] * gx_t[(size_t)s_idx[e] * DIN + t];
    float acc = (a0 + a1) + (a2 + a3);
    float dj = gx_dis[j];
    float v = dj * acc + dj * dj * gx_t[(size_t)j * DIN + t]
            + b2[t] + x[(size_t)j * DIN + t];
    out[(size_t)j * DIN + t] = 1.f / (1.f + expf(-sigp[0] * v));
}

// ----------------- bf16-split tensor-core GEMM with inline A split -----------
// C[M,N] = A[M,K] * B[K,N]. A is fp32 row-major (split to hi/lo bf16 in the
// tile loader — same split_one math as before, bit-identical accumulators).
// B is pre-split transposed hi/lo bf16 [N][K].
// EPI 1: relu(C + bias) -> fp32 out.   EPI 0: raw C -> fp32 out (no bias).
#define BM 128
#define BN 64
#define ASTR 24
#define BSTR 24

__device__ __forceinline__ void mma16816(float c[4], const unsigned a[4], const unsigned b[2]) {
    asm volatile(
        "mma.sync.aligned.m16n8k16.row.col.f32.bf16.bf16.f32 "
        "{%0,%1,%2,%3}, {%4,%5,%6,%7}, {%8,%9}, {%0,%1,%2,%3};\n"
        : "+f"(c[0]), "+f"(c[1]), "+f"(c[2]), "+f"(c[3])
        : "r"(a[0]), "r"(a[1]), "r"(a[2]), "r"(a[3]), "r"(b[0]), "r"(b[1]));
}

__device__ __forceinline__ unsigned pack2(__nv_bfloat16 a, __nv_bfloat16 b) {
    __nv_bfloat162 t;
    t.x = a; t.y = b;
    return *(unsigned*)&t;
}

template <int EPI>
__device__ __forceinline__ void gemm_core(const float* __restrict__ Af,
                                          const __nv_bfloat16* __restrict__ Bth,
                                          const __nv_bfloat16* __restrict__ Btl,
                                          const float* __restrict__ bias,
                                          float* __restrict__ out,
                                          int K, int N) {
    __shared__ __nv_bfloat16 AsH[BM * ASTR], AsL[BM * ASTR];
    __shared__ __nv_bfloat16 BsH[BN * BSTR], BsL[BN * BSTR];

    int tid  = threadIdx.x;
    int warp = tid >> 5, lane = tid & 31;
    int wm = warp >> 1, wn = warp & 1;   // 4 (m) x 2 (n) warps
    int gr = lane >> 2, tc = lane & 3;
    int m0 = blockIdx.x * BM, n0 = blockIdx.y * BN;

    float c[2][4][4];
#pragma unroll
    for (int a = 0; a < 2; a++)
#pragma unroll
        for (int b = 0; b < 4; b++)
#pragma unroll
            for (int q = 0; q < 4; q++) c[a][b][q] = 0.f;

    int arow = tid >> 1, ahalf = tid & 1;        // 128 rows x 2 halves of 8
    int brow = (tid & 127) >> 1, bhalf = tid & 1;

    for (int k0 = 0; k0 < K; k0 += 16) {
        __syncthreads();
        // A tile 128x16: load fp32, split to hi/lo bf16 in registers.
        {
            const float4* pA = (const float4*)(Af + (size_t)(m0 + arow) * K + k0 + ahalf * 8);
            float4 f0 = pA[0];
            float4 f1 = pA[1];
            __nv_bfloat16 h[8], l[8];
            split_one(f0.x, &h[0], &l[0]);
            split_one(f0.y, &h[1], &l[1]);
            split_one(f0.z, &h[2], &l[2]);
            split_one(f0.w, &h[3], &l[3]);
            split_one(f1.x, &h[4], &l[4]);
            split_one(f1.y, &h[5], &l[5]);
            split_one(f1.z, &h[6], &l[6]);
            split_one(f1.w, &h[7], &l[7]);
            uint4 uh, ul;
            uh.x = pack2(h[0], h[1]); uh.y = pack2(h[2], h[3]);
            uh.z = pack2(h[4], h[5]); uh.w = pack2(h[6], h[7]);
            ul.x = pack2(l[0], l[1]); ul.y = pack2(l[2], l[3]);
            ul.z = pack2(l[4], l[5]); ul.w = pack2(l[6], l[7]);
            *(uint4*)(AsH + arow * ASTR + ahalf * 8) = uh;
            *(uint4*)(AsL + arow * ASTR + ahalf * 8) = ul;
        }
        // B tile 64x16 (pre-split transposed weights)
        if (tid < 128) {
            const uint4* pH = (const uint4*)(Bth + (size_t)(n0 + brow) * K + k0 + bhalf * 8);
            const uint4* pL = (const uint4*)(Btl + (size_t)(n0 + brow) * K + k0 + bhalf * 8);
            *(uint4*)(BsH + brow * BSTR + bhalf * 8) = *pH;
            *(uint4*)(BsL + brow * BSTR + bhalf * 8) = *pL;
        }
        __syncthreads();

        unsigned aH[2][4], aL[2][4], bH[4][2], bL[4][2];
#pragma unroll
        for (int mf = 0; mf < 2; mf++) {
            int r = wm * 32 + mf * 16 + gr;
            const __nv_bfloat16* pH = AsH + r * ASTR + tc * 2;
            const __nv_bfloat16* pL = AsL + r * ASTR + tc * 2;
            aH[mf][0] = *(const unsigned*)(pH);
            aH[mf][1] = *(const unsigned*)(pH + 8 * ASTR);
            aH[mf][2] = *(const unsigned*)(pH + 8);
            aH[mf][3] = *(const unsigned*)(pH + 8 * ASTR + 8);
            aL[mf][0] = *(const unsigned*)(pL);
            aL[mf][1] = *(const unsigned*)(pL + 8 * ASTR);
            aL[mf][2] = *(const unsigned*)(pL + 8);
            aL[mf][3] = *(const unsigned*)(pL + 8 * ASTR + 8);
        }
#pragma unroll
        for (int nf = 0; nf < 4; nf++) {
            int n = wn * 32 + nf * 8 + gr;
            const __nv_bfloat16* pH = BsH + n * BSTR + tc * 2;
            const __nv_bfloat16* pL = BsL + n * BSTR + tc * 2;
            bH[nf][0] = *(const unsigned*)(pH);
            bH[nf][1] = *(const unsigned*)(pH + 8);
            bL[nf][0] = *(const unsigned*)(pL);
            bL[nf][1] = *(const unsigned*)(pL + 8);
        }
#pragma unroll
        for (int mf = 0; mf < 2; mf++)
#pragma unroll
            for (int nf = 0; nf < 4; nf++) {
                mma16816(c[mf][nf], aH[mf], bH[nf]);  // hi*hi
                mma16816(c[mf][nf], aH[mf], bL[nf]);  // hi*lo
                mma16816(c[mf][nf], aL[mf], bH[nf]);  // lo*hi
            }
    }

#pragma unroll
    for (int mf = 0; mf < 2; mf++) {
#pragma unroll
        for (int nf = 0; nf < 4; nf++) {
            int row0 = m0 + wm * 32 + mf * 16 + gr;
            int col0 = n0 + wn * 32 + nf * 8 + tc * 2;
#pragma unroll
            for (int h = 0; h < 2; h++) {
                int r = row0 + h * 8;
#pragma unroll
                for (int q = 0; q < 2; q++) {
                    int cc = col0 + q;
                    float v = c[mf][nf][h * 2 + q];
                    if (EPI == 1) v = fmaxf(v + bias[cc], 0.f);
                    out[(size_t)r * N + cc] = v;
                }
            }
        }
    }
}

__global__ void __launch_bounds__(256) kx_gemm1(const float* __restrict__ b1) {
    gemm_core<1>(gx_p1, gx_w1h, gx_w1l, b1, gx_h, DIN, HID);
}
__global__ void __launch_bounds__(256) kx_gemm2() {
    gemm_core<0>(gx_h, gx_w2h, gx_w2l, nullptr, gx_t, HID, DIN);
}

// ---------------------------------------------------------------------------
extern "C" void kernel_launch(void* const* d_in, const int* in_sizes, int n_in,
                              void* d_out, int out_size) {
    const float* A  = (const float*)d_in[0];
    const float* x  = (const float*)d_in[1];
    const float* W1 = (const float*)d_in[2];
    const float* b1 = (const float*)d_in[3];
    const float* W2 = (const float*)d_in[4];
    const float* b2 = (const float*)d_in[5];
    const float* sp = (const float*)d_in[6];
    float* out = (float*)d_out;

    kx_zero_cnt<<<32, 256>>>();
    kx_extract<<<8192, 256>>>((const float4*)A);
    kx_dis<<<32, 256>>>();
    kx_tsplit_w1<<<256, 256>>>(W1);
    kx_tsplit_w2<<<256, 256>>>(W2);
    kx_prop1<<<NN, DIN>>>(x);
    kx_gemm1<<<dim3(NN / BM, HID / BN), 256>>>(b1);
    kx_gemm2<<<dim3(NN / BM, DIN / BN), 256>>>();
    kx_prop2epi<<<NN, DIN>>>(x, b2, sp, out);
}

// round 16
// speedup vs baseline: 1.0336x; 1.0336x over previous
#include <cuda_runtime.h>
#include <cuda_bf16.h>
#include <math.h>
#include <stdint.h>

// Problem constants
#define NN   8192
#define DIN  256
#define HID  512
#define CAP  128   // max stored in-edges per column (avg 32, max ~60 statistically)

// ---------------- device scratch (no runtime allocation allowed) -------------
__device__ int   gx_cnt[NN];
__device__ int   gx_ell[NN * CAP];
__device__ float gx_dis[NN];
__device__ float gx_p1[NN * DIN];          // propagate(x) fp32
__device__ float gx_h [NN * HID];          // relu(layer1) fp32
__device__ float gx_t [NN * DIN];          // h @ W2 fp32 (pre-propagate)
__device__ __nv_bfloat16 gx_w1h[HID * DIN], gx_w1l[HID * DIN]; // W1^T: [n<512][k<256]
__device__ __nv_bfloat16 gx_w2h[DIN * HID], gx_w2l[DIN * HID]; // W2^T: [n<256][k<512]

// ---------------------------------------------------------------------------
__global__ void kx_zero_cnt() {
    int i = blockIdx.x * blockDim.x + threadIdx.x;
    if (i < NN) gx_cnt[i] = 0;
}

// Scan dense A (row-major [i][j]) as float4, push nonzeros into per-column ELL.
__global__ void kx_extract(const float4* __restrict__ A4) {
    const int total = NN * NN / 4;  // 16777216
    for (int idx = blockIdx.x * blockDim.x + threadIdx.x; idx < total;
         idx += gridDim.x * blockDim.x) {
        float4 v = __ldcs(&A4[idx]);   // streaming: don't pollute L2
        if (v.x == 0.f && v.y == 0.f && v.z == 0.f && v.w == 0.f) continue;
        int base = idx << 2;
        int i = base >> 13;        // row
        int j = base & (NN - 1);   // col
        if (v.x != 0.f) { int s = atomicAdd(&gx_cnt[j],     1); if (s < CAP) gx_ell[(j    ) * CAP + s] = i; }
        if (v.y != 0.f) { int s = atomicAdd(&gx_cnt[j + 1], 1); if (s < CAP) gx_ell[(j + 1) * CAP + s] = i; }
        if (v.z != 0.f) { int s = atomicAdd(&gx_cnt[j + 2], 1); if (s < CAP) gx_ell[(j + 2) * CAP + s] = i; }
        if (v.w != 0.f) { int s = atomicAdd(&gx_cnt[j + 3], 1); if (s < CAP) gx_ell[(j + 3) * CAP + s] = i; }
    }
}

__global__ void kx_dis() {
    int j = blockIdx.x * blockDim.x + threadIdx.x;
    if (j < NN) {
        float deg = (float)gx_cnt[j] + 1.0f;   // self loop
        gx_dis[j] = rsqrtf(deg);
    }
}

// ----------------- split helpers (fp32 -> bf16 hi + bf16 lo) -----------------
__device__ __forceinline__ void split_one(float v, __nv_bfloat16* hi, __nv_bfloat16* lo) {
    __nv_bfloat16 h = __float2bfloat16(v);
    *hi = h;
    *lo = __float2bfloat16(v - __bfloat162float(h));
}

// One (n, k-pair) of the weight transpose+split.
__device__ __forceinline__ void tsplit_pair(const float* __restrict__ W,
                                            __nv_bfloat16* __restrict__ th,
                                            __nv_bfloat16* __restrict__ tl,
                                            int K, int Nc, int idx) {
    int kh = K >> 1;
    int n = idx / kh;
    int k = (idx - n * kh) << 1;
    float v0 = W[(size_t)k * Nc + n];
    float v1 = W[(size_t)(k + 1) * Nc + n];
    __nv_bfloat16 h0, l0, h1, l1;
    split_one(v0, &h0, &l0);
    split_one(v1, &h1, &l1);
    __nv_bfloat162 hp, lp;
    hp.x = h0; hp.y = h1;
    lp.x = l0; lp.y = l1;
    size_t o = (size_t)n * K + k;
    *(__nv_bfloat162*)(th + o) = hp;
    *(__nv_bfloat162*)(tl + o) = lp;
}

// Both weight transforms in ONE launch. W1 pairs: HID*DIN/2 = 65536; W2 same.
__global__ void kx_tsplit_both(const float* __restrict__ W1,
                               const float* __restrict__ W2) {
    int idx = blockIdx.x * blockDim.x + threadIdx.x;  // grid 512*256 = 131072
    if (idx < 65536) tsplit_pair(W1, gx_w1h, gx_w1l, DIN, HID, idx);
    else             tsplit_pair(W2, gx_w2h, gx_w2l, HID, DIN, idx - 65536);
}

// ----------------- sparse propagate (layer 1, fp32 out; proven) --------------
__global__ void kx_prop1(const float* __restrict__ x) {
    __shared__ int   s_idx[CAP];
    __shared__ float s_w[CAP];
    int j = blockIdx.x;
    int t = threadIdx.x;           // d = DIN
    int cnt = gx_cnt[j];
    if (cnt > CAP) cnt = CAP;
    if (t < cnt) {
        int i = gx_ell[j * CAP + t];
        s_idx[t] = i;
        s_w[t]   = gx_dis[i];
    }
    __syncthreads();
    float a0 = 0.f, a1 = 0.f, a2 = 0.f, a3 = 0.f;
    int e = 0;
    for (; e + 4 <= cnt; e += 4) {
        a0 += s_w[e]     * x[(size_t)s_idx[e]     * DIN + t];
        a1 += s_w[e + 1] * x[(size_t)s_idx[e + 1] * DIN + t];
        a2 += s_w[e + 2] * x[(size_t)s_idx[e + 2] * DIN + t];
        a3 += s_w[e + 3] * x[(size_t)s_idx[e + 3] * DIN + t];
    }
    for (; e < cnt; e++)
        a0 += s_w[e] * x[(size_t)s_idx[e] * DIN + t];
    float acc = (a0 + a1) + (a2 + a3);
    float dj = gx_dis[j];
    gx_p1[(size_t)j * DIN + t] = dj * acc + dj * dj * x[(size_t)j * DIN + t];
}

// ----------------- layer-2 propagate + full epilogue (d = 256) ---------------
// out[j,t] = sigmoid(sp * (dj*sum_i dis_i*t_i + dj^2*t_j + b2[t] + x[j,t]))
__global__ void kx_prop2epi(const float* __restrict__ x,
                            const float* __restrict__ b2,
                            const float* __restrict__ sigp,
                            float* __restrict__ out) {
    __shared__ int   s_idx[CAP];
    __shared__ float s_w[CAP];
    int j = blockIdx.x;
    int t = threadIdx.x;           // d = DIN
    int cnt = gx_cnt[j];
    if (cnt > CAP) cnt = CAP;
    if (t < cnt) {
        int i = gx_ell[j * CAP + t];
        s_idx[t] = i;
        s_w[t]   = gx_dis[i];
    }
    __syncthreads();
    float a0 = 0.f, a1 = 0.f, a2 = 0.f, a3 = 0.f;
    int e = 0;
    for (; e + 4 <= cnt; e += 4) {
        a0 += s_w[e]     * gx_t[(size_t)s_idx[e]     * DIN + t];
        a1 += s_w[e + 1] * gx_t[(size_t)s_idx[e + 1] * DIN + t];
        a2 += s_w[e + 2] * gx_t[(size_t)s_idx[e + 2] * DIN + t];
        a3 += s_w[e + 3] * gx_t[(size_t)s_idx[e + 3] * DIN + t];
    }
    for (; e < cnt; e++)
        a0 += s_w[e] * gx_t[(size_t)s_idx[e] * DIN + t];
    float acc = (a0 + a1) + (a2 + a3);
    float dj = gx_dis[j];
    float v = dj * acc + dj * dj * gx_t[(size_t)j * DIN + t]
            + b2[t] + x[(size_t)j * DIN + t];
    out[(size_t)j * DIN + t] = 1.f / (1.f + expf(-sigp[0] * v));
}

// ----------------- pipelined bf16-split tensor-core GEMM ---------------------
// C[M,N] = A[M,K] * B[K,N]. A fp32 row-major (inline hi/lo split in the tile
// loader). B pre-split transposed hi/lo bf16 [N][K]. 2-stage smem ping-pong
// with register prefetch: global loads for tile k+1 issue before tile k's mmas.
// EPI 1: relu(C + bias) -> fp32 out.   EPI 0: raw C -> fp32 out (no bias).
#define BM 128
#define BN 64
#define ASTR 24
#define BSTR 24

__device__ __forceinline__ void mma16816(float c[4], const unsigned a[4], const unsigned b[2]) {
    asm volatile(
        "mma.sync.aligned.m16n8k16.row.col.f32.bf16.bf16.f32 "
        "{%0,%1,%2,%3}, {%4,%5,%6,%7}, {%8,%9}, {%0,%1,%2,%3};\n"
        : "+f"(c[0]), "+f"(c[1]), "+f"(c[2]), "+f"(c[3])
        : "r"(a[0]), "r"(a[1]), "r"(a[2]), "r"(a[3]), "r"(b[0]), "r"(b[1]));
}

__device__ __forceinline__ unsigned pack2(__nv_bfloat16 a, __nv_bfloat16 b) {
    __nv_bfloat162 t;
    t.x = a; t.y = b;
    return *(unsigned*)&t;
}

__device__ __forceinline__ void cvt_store_a(__nv_bfloat16* dstH, __nv_bfloat16* dstL,
                                            float4 f0, float4 f1) {
    __nv_bfloat16 h[8], l[8];
    split_one(f0.x, &h[0], &l[0]);
    split_one(f0.y, &h[1], &l[1]);
    split_one(f0.z, &h[2], &l[2]);
    split_one(f0.w, &h[3], &l[3]);
    split_one(f1.x, &h[4], &l[4]);
    split_one(f1.y, &h[5], &l[5]);
    split_one(f1.z, &h[6], &l[6]);
    split_one(f1.w, &h[7], &l[7]);
    uint4 uh, ul;
    uh.x = pack2(h[0], h[1]); uh.y = pack2(h[2], h[3]);
    uh.z = pack2(h[4], h[5]); uh.w = pack2(h[6], h[7]);
    ul.x = pack2(l[0], l[1]); ul.y = pack2(l[2], l[3]);
    ul.z = pack2(l[4], l[5]); ul.w = pack2(l[6], l[7]);
    *(uint4*)dstH = uh;
    *(uint4*)dstL = ul;
}

template <int EPI>
__device__ __forceinline__ void gemm_core(const float* __restrict__ Af,
                                          const __nv_bfloat16* __restrict__ Bth,
                                          const __nv_bfloat16* __restrict__ Btl,
                                          const float* __restrict__ bias,
                                          float* __restrict__ out,
                                          int K, int N) {
    __shared__ __nv_bfloat16 AsH[2][BM * ASTR], AsL[2][BM * ASTR];
    __shared__ __nv_bfloat16 BsH[2][BN * BSTR], BsL[2][BN * BSTR];

    int tid  = threadIdx.x;
    int warp = tid >> 5, lane = tid & 31;
    int wm = warp >> 1, wn = warp & 1;   // 4 (m) x 2 (n) warps
    int gr = lane >> 2, tc = lane & 3;
    int m0 = blockIdx.x * BM, n0 = blockIdx.y * BN;

    float c[2][4][4];
#pragma unroll
    for (int a = 0; a < 2; a++)
#pragma unroll
        for (int b = 0; b < 4; b++)
#pragma unroll
            for (int q = 0; q < 4; q++) c[a][b][q] = 0.f;

    int arow = tid >> 1, ahalf = tid & 1;        // 128 rows x 2 halves of 8
    int brow = (tid & 127) >> 1, bhalf = tid & 1;
    const int KT = K >> 4;

    const float* aBase = Af + (size_t)(m0 + arow) * K + ahalf * 8;
    const __nv_bfloat16* bhBase = Bth + (size_t)(n0 + brow) * K + bhalf * 8;
    const __nv_bfloat16* blBase = Btl + (size_t)(n0 + brow) * K + bhalf * 8;
    int aSlot = arow * ASTR + ahalf * 8;
    int bSlot = brow * BSTR + bhalf * 8;

    // Prologue: tile 0 -> stage 0
    {
        const float4* pA = (const float4*)(aBase);
        float4 f0 = pA[0], f1 = pA[1];
        cvt_store_a(&AsH[0][aSlot], &AsL[0][aSlot], f0, f1);
        if (tid < 128) {
            *(uint4*)(&BsH[0][bSlot]) = *(const uint4*)(bhBase);
            *(uint4*)(&BsL[0][bSlot]) = *(const uint4*)(blBase);
        }
    }
    __syncthreads();

    for (int kt = 0; kt < KT; kt++) {
        int cur = kt & 1;
        int nk = kt + 1;
        bool have = nk < KT;

        // Prefetch next tile's globals into registers (overlaps with mmas below).
        float4 na0, na1;
        uint4 nbh, nbl;
        if (have) {
            const float4* pA = (const float4*)(aBase + (nk << 4));
            na0 = pA[0];
            na1 = pA[1];
            if (tid < 128) {
                nbh = *(const uint4*)(bhBase + (nk << 4));
                nbl = *(const uint4*)(blBase + (nk << 4));
            }
        }

        // Fragment loads from current stage.
        unsigned aH[2][4], aL[2][4], bH[4][2], bL[4][2];
#pragma unroll
        for (int mf = 0; mf < 2; mf++) {
            int r = wm * 32 + mf * 16 + gr;
            const __nv_bfloat16* pH = &AsH[cur][r * ASTR + tc * 2];
            const __nv_bfloat16* pL = &AsL[cur][r * ASTR + tc * 2];
            aH[mf][0] = *(const unsigned*)(pH);
            aH[mf][1] = *(const unsigned*)(pH + 8 * ASTR);
            aH[mf][2] = *(const unsigned*)(pH + 8);
            aH[mf][3] = *(const unsigned*)(pH + 8 * ASTR + 8);
            aL[mf][0] = *(const unsigned*)(pL);
            aL[mf][1] = *(const unsigned*)(pL + 8 * ASTR);
            aL[mf][2] = *(const unsigned*)(pL + 8);
            aL[mf][3] = *(const unsigned*)(pL + 8 * ASTR + 8);
        }
#pragma unroll
        for (int nf = 0; nf < 4; nf++) {
            int n = wn * 32 + nf * 8 + gr;
            const __nv_bfloat16* pH = &BsH[cur][n * BSTR + tc * 2];
            const __nv_bfloat16* pL = &BsL[cur][n * BSTR + tc * 2];
            bH[nf][0] = *(const unsigned*)(pH);
            bH[nf][1] = *(const unsigned*)(pH + 8);
            bL[nf][0] = *(const unsigned*)(pL);
            bL[nf][1] = *(const unsigned*)(pL + 8);
        }
#pragma unroll
        for (int mf = 0; mf < 2; mf++)
#pragma unroll
            for (int nf = 0; nf < 4; nf++) {
                mma16816(c[mf][nf], aH[mf], bH[nf]);  // hi*hi
                mma16816(c[mf][nf], aH[mf], bL[nf]);  // hi*lo
                mma16816(c[mf][nf], aL[mf], bH[nf]);  // lo*hi
            }

        // Store prefetched tile into the other stage.
        if (have) {
            int nxt = nk & 1;
            cvt_store_a(&AsH[nxt][aSlot], &AsL[nxt][aSlot], na0, na1);
            if (tid < 128) {
                *(uint4*)(&BsH[nxt][bSlot]) = nbh;
                *(uint4*)(&BsL[nxt][bSlot]) = nbl;
            }
        }
        __syncthreads();
    }

#pragma unroll
    for (int mf = 0; mf < 2; mf++) {
#pragma unroll
        for (int nf = 0; nf < 4; nf++) {
            int row0 = m0 + wm * 32 + mf * 16 + gr;
            int col0 = n0 + wn * 32 + nf * 8 + tc * 2;
#pragma unroll
            for (int h = 0; h < 2; h++) {
                int r = row0 + h * 8;
#pragma unroll
                for (int q = 0; q < 2; q++) {
                    int cc = col0 + q;
                    float v = c[mf][nf][h * 2 + q];
                    if (EPI == 1) v = fmaxf(v + bias[cc], 0.f);
                    out[(size_t)r * N + cc] = v;
                }
            }
        }
    }
}

__global__ void __launch_bounds__(256) kx_gemm1(const float* __restrict__ b1) {
    gemm_core<1>(gx_p1, gx_w1h, gx_w1l, b1, gx_h, DIN, HID);
}
__global__ void __launch_bounds__(256) kx_gemm2() {
    gemm_core<0>(gx_h, gx_w2h, gx_w2l, nullptr, gx_t, HID, DIN);
}

// ---------------------------------------------------------------------------
extern "C" void kernel_launch(void* const* d_in, const int* in_sizes, int n_in,
                              void* d_out, int out_size) {
    const float* A  = (const float*)d_in[0];
    const float* x  = (const float*)d_in[1];
    const float* W1 = (const float*)d_in[2];
    const float* b1 = (const float*)d_in[3];
    const float* W2 = (const float*)d_in[4];
    const float* b2 = (const float*)d_in[5];
    const float* sp = (const float*)d_in[6];
    float* out = (float*)d_out;

    kx_zero_cnt<<<32, 256>>>();                     // 0
    kx_extract<<<8192, 256>>>((const float4*)A);    // 1
    kx_dis<<<32, 256>>>();                          // 2
    kx_prop1<<<NN, DIN>>>(x);                       // 3  <- profiled slot
    kx_tsplit_both<<<512, 256>>>(W1, W2);           // 4
    kx_gemm1<<<dim3(NN / BM, HID / BN), 256>>>(b1); // 5
    kx_gemm2<<<dim3(NN / BM, DIN / BN), 256>>>();   // 6
    kx_prop2epi<<<NN, DIN>>>(x, b2, sp, out);       // 7
}

// round 17
// speedup vs baseline: 1.1245x; 1.0879x over previous
#include <cuda_runtime.h>
#include <cuda_bf16.h>
#include <math.h>
#include <stdint.h>

// Problem constants
#define NN   8192
#define DIN  256
#define HID  512
#define CAP  128   // max stored in-edges per column (avg 32, max ~60 statistically)

// ---------------- device scratch (no runtime allocation allowed) -------------
__device__ int   gx_cnt[NN];
__device__ int   gx_ell[NN * CAP];
__device__ float gx_dis[NN];
__device__ float gx_p1[NN * DIN];          // propagate(x) fp32
__device__ float gx_h [NN * HID];          // relu(layer1) fp32
__device__ float gx_t [NN * DIN];          // h @ W2 fp32 (pre-propagate)
__device__ __nv_bfloat16 gx_w1h[HID * DIN], gx_w1l[HID * DIN]; // W1^T: [n<512][k<256]
__device__ __nv_bfloat16 gx_w2h[DIN * HID], gx_w2l[DIN * HID]; // W2^T: [n<256][k<512]

// ---------------------------------------------------------------------------
__global__ void kx_zero_cnt() {
    int i = blockIdx.x * blockDim.x + threadIdx.x;
    if (i < NN) gx_cnt[i] = 0;
}

// Scan dense A (row-major [i][j]) as float4, push nonzeros into per-column ELL.
__global__ void kx_extract(const float4* __restrict__ A4) {
    const int total = NN * NN / 4;  // 16777216
    for (int idx = blockIdx.x * blockDim.x + threadIdx.x; idx < total;
         idx += gridDim.x * blockDim.x) {
        float4 v = __ldcs(&A4[idx]);   // streaming: don't pollute L2
        if (v.x == 0.f && v.y == 0.f && v.z == 0.f && v.w == 0.f) continue;
        int base = idx << 2;
        int i = base >> 13;        // row
        int j = base & (NN - 1);   // col
        if (v.x != 0.f) { int s = atomicAdd(&gx_cnt[j],     1); if (s < CAP) gx_ell[(j    ) * CAP + s] = i; }
        if (v.y != 0.f) { int s = atomicAdd(&gx_cnt[j + 1], 1); if (s < CAP) gx_ell[(j + 1) * CAP + s] = i; }
        if (v.z != 0.f) { int s = atomicAdd(&gx_cnt[j + 2], 1); if (s < CAP) gx_ell[(j + 2) * CAP + s] = i; }
        if (v.w != 0.f) { int s = atomicAdd(&gx_cnt[j + 3], 1); if (s < CAP) gx_ell[(j + 3) * CAP + s] = i; }
    }
}

__global__ void kx_dis() {
    int j = blockIdx.x * blockDim.x + threadIdx.x;
    if (j < NN) {
        float deg = (float)gx_cnt[j] + 1.0f;   // self loop
        gx_dis[j] = rsqrtf(deg);
    }
}

// ----------------- split helpers (fp32 -> bf16 hi + bf16 lo) -----------------
__device__ __forceinline__ void split_one(float v, __nv_bfloat16* hi, __nv_bfloat16* lo) {
    __nv_bfloat16 h = __float2bfloat16(v);
    *hi = h;
    *lo = __float2bfloat16(v - __bfloat162float(h));
}

// One (n, k-pair) of the weight transpose+split.
__device__ __forceinline__ void tsplit_pair(const float* __restrict__ W,
                                            __nv_bfloat16* __restrict__ th,
                                            __nv_bfloat16* __restrict__ tl,
                                            int K, int Nc, int idx) {
    int kh = K >> 1;
    int n = idx / kh;
    int k = (idx - n * kh) << 1;
    float v0 = W[(size_t)k * Nc + n];
    float v1 = W[(size_t)(k + 1) * Nc + n];
    __nv_bfloat16 h0, l0, h1, l1;
    split_one(v0, &h0, &l0);
    split_one(v1, &h1, &l1);
    __nv_bfloat162 hp, lp;
    hp.x = h0; hp.y = h1;
    lp.x = l0; lp.y = l1;
    size_t o = (size_t)n * K + k;
    *(__nv_bfloat162*)(th + o) = hp;
    *(__nv_bfloat162*)(tl + o) = lp;
}

// Both weight transforms in ONE launch. W1 pairs: HID*DIN/2 = 65536; W2 same.
__global__ void kx_tsplit_both(const float* __restrict__ W1,
                               const float* __restrict__ W2) {
    int idx = blockIdx.x * blockDim.x + threadIdx.x;  // grid 512*256 = 131072
    if (idx < 65536) tsplit_pair(W1, gx_w1h, gx_w1l, DIN, HID, idx);
    else             tsplit_pair(W2, gx_w2h, gx_w2l, HID, DIN, idx - 65536);
}

// ----------------- vectorized sparse propagate (float4/thread) ---------------
// Block = 64 threads; thread t owns columns [4t, 4t+4) of row j = blockIdx.x.
// s_off holds precomputed row offsets (idx*DIN) to kill per-edge IMADs.
// Same accumulator structure / order as before -> bit-identical results.
__global__ void __launch_bounds__(64) kx_prop1(const float* __restrict__ x) {
    __shared__ int   s_off[CAP];
    __shared__ float s_w[CAP];
    int j = blockIdx.x;
    int t = threadIdx.x;
    int cnt = gx_cnt[j];
    if (cnt > CAP) cnt = CAP;
    for (int e = t; e < cnt; e += 64) {
        int i = gx_ell[j * CAP + e];
        s_off[e] = i * DIN;
        s_w[e]   = gx_dis[i];
    }
    __syncthreads();
    int col = t << 2;
    float4 a0 = {0.f, 0.f, 0.f, 0.f}, a1 = {0.f, 0.f, 0.f, 0.f};
    float4 a2 = {0.f, 0.f, 0.f, 0.f}, a3 = {0.f, 0.f, 0.f, 0.f};
    int e = 0;
    for (; e + 4 <= cnt; e += 4) {
        float4 v0 = *(const float4*)(x + s_off[e]     + col);
        float4 v1 = *(const float4*)(x + s_off[e + 1] + col);
        float4 v2 = *(const float4*)(x + s_off[e + 2] + col);
        float4 v3 = *(const float4*)(x + s_off[e + 3] + col);
        float w0 = s_w[e], w1 = s_w[e + 1], w2 = s_w[e + 2], w3 = s_w[e + 3];
        a0.x += w0 * v0.x; a0.y += w0 * v0.y; a0.z += w0 * v0.z; a0.w += w0 * v0.w;
        a1.x += w1 * v1.x; a1.y += w1 * v1.y; a1.z += w1 * v1.z; a1.w += w1 * v1.w;
        a2.x += w2 * v2.x; a2.y += w2 * v2.y; a2.z += w2 * v2.z; a2.w += w2 * v2.w;
        a3.x += w3 * v3.x; a3.y += w3 * v3.y; a3.z += w3 * v3.z; a3.w += w3 * v3.w;
    }
    for (; e < cnt; e++) {
        float4 v = *(const float4*)(x + s_off[e] + col);
        float w = s_w[e];
        a0.x += w * v.x; a0.y += w * v.y; a0.z += w * v.z; a0.w += w * v.w;
    }
    float dj = gx_dis[j];
    float dj2 = dj * dj;
    float4 sv = *(const float4*)(x + j * DIN + col);
    float4 r;
    r.x = dj * ((a0.x + a1.x) + (a2.x + a3.x)) + dj2 * sv.x;
    r.y = dj * ((a0.y + a1.y) + (a2.y + a3.y)) + dj2 * sv.y;
    r.z = dj * ((a0.z + a1.z) + (a2.z + a3.z)) + dj2 * sv.z;
    r.w = dj * ((a0.w + a1.w) + (a2.w + a3.w)) + dj2 * sv.w;
    *(float4*)(gx_p1 + j * DIN + col) = r;
}

// Layer-2 propagate + bias + skip + sigmoid, vectorized identically.
__global__ void __launch_bounds__(64) kx_prop2epi(const float* __restrict__ x,
                                                  const float* __restrict__ b2,
                                                  const float* __restrict__ sigp,
                                                  float* __restrict__ out) {
    __shared__ int   s_off[CAP];
    __shared__ float s_w[CAP];
    int j = blockIdx.x;
    int t = threadIdx.x;
    int cnt = gx_cnt[j];
    if (cnt > CAP) cnt = CAP;
    for (int e = t; e < cnt; e += 64) {
        int i = gx_ell[j * CAP + e];
        s_off[e] = i * DIN;
        s_w[e]   = gx_dis[i];
    }
    __syncthreads();
    int col = t << 2;
    float4 a0 = {0.f, 0.f, 0.f, 0.f}, a1 = {0.f, 0.f, 0.f, 0.f};
    float4 a2 = {0.f, 0.f, 0.f, 0.f}, a3 = {0.f, 0.f, 0.f, 0.f};
    int e = 0;
    for (; e + 4 <= cnt; e += 4) {
        float4 v0 = *(const float4*)(gx_t + s_off[e]     + col);
        float4 v1 = *(const float4*)(gx_t + s_off[e + 1] + col);
        float4 v2 = *(const float4*)(gx_t + s_off[e + 2] + col);
        float4 v3 = *(const float4*)(gx_t + s_off[e + 3] + col);
        float w0 = s_w[e], w1 = s_w[e + 1], w2 = s_w[e + 2], w3 = s_w[e + 3];
        a0.x += w0 * v0.x; a0.y += w0 * v0.y; a0.z += w0 * v0.z; a0.w += w0 * v0.w;
        a1.x += w1 * v1.x; a1.y += w1 * v1.y; a1.z += w1 * v1.z; a1.w += w1 * v1.w;
        a2.x += w2 * v2.x; a2.y += w2 * v2.y; a2.z += w2 * v2.z; a2.w += w2 * v2.w;
        a3.x += w3 * v3.x; a3.y += w3 * v3.y; a3.z += w3 * v3.z; a3.w += w3 * v3.w;
    }
    for (; e < cnt; e++) {
        float4 v = *(const float4*)(gx_t + s_off[e] + col);
        float w = s_w[e];
        a0.x += w * v.x; a0.y += w * v.y; a0.z += w * v.z; a0.w += w * v.w;
    }
    float dj = gx_dis[j];
    float dj2 = dj * dj;
    float sp = sigp[0];
    float4 sv = *(const float4*)(gx_t + j * DIN + col);
    float4 bv = *(const float4*)(b2 + col);
    float4 xv = *(const float4*)(x + j * DIN + col);
    float4 r;
    r.x = dj * ((a0.x + a1.x) + (a2.x + a3.x)) + dj2 * sv.x + bv.x + xv.x;
    r.y = dj * ((a0.y + a1.y) + (a2.y + a3.y)) + dj2 * sv.y + bv.y + xv.y;
    r.z = dj * ((a0.z + a1.z) + (a2.z + a3.z)) + dj2 * sv.z + bv.z + xv.z;
    r.w = dj * ((a0.w + a1.w) + (a2.w + a3.w)) + dj2 * sv.w + bv.w + xv.w;
    r.x = 1.f / (1.f + expf(-sp * r.x));
    r.y = 1.f / (1.f + expf(-sp * r.y));
    r.z = 1.f / (1.f + expf(-sp * r.z));
    r.w = 1.f / (1.f + expf(-sp * r.w));
    *(float4*)(out + j * DIN + col) = r;
}

// ----------------- pipelined bf16-split tensor-core GEMM ---------------------
// C[M,N] = A[M,K] * B[K,N]. A fp32 row-major (inline hi/lo split in the tile
// loader). B pre-split transposed hi/lo bf16 [N][K]. 2-stage smem ping-pong
// with register prefetch.
// EPI 1: relu(C + bias) -> fp32 out.   EPI 0: raw C -> fp32 out (no bias).
#define BM 128
#define BN 64
#define ASTR 24
#define BSTR 24

__device__ __forceinline__ void mma16816(float c[4], const unsigned a[4], const unsigned b[2]) {
    asm volatile(
        "mma.sync.aligned.m16n8k16.row.col.f32.bf16.bf16.f32 "
        "{%0,%1,%2,%3}, {%4,%5,%6,%7}, {%8,%9}, {%0,%1,%2,%3};\n"
        : "+f"(c[0]), "+f"(c[1]), "+f"(c[2]), "+f"(c[3])
        : "r"(a[0]), "r"(a[1]), "r"(a[2]), "r"(a[3]), "r"(b[0]), "r"(b[1]));
}

__device__ __forceinline__ unsigned pack2(__nv_bfloat16 a, __nv_bfloat16 b) {
    __nv_bfloat162 t;
    t.x = a; t.y = b;
    return *(unsigned*)&t;
}

__device__ __forceinline__ void cvt_store_a(__nv_bfloat16* dstH, __nv_bfloat16* dstL,
                                            float4 f0, float4 f1) {
    __nv_bfloat16 h[8], l[8];
    split_one(f0.x, &h[0], &l[0]);
    split_one(f0.y, &h[1], &l[1]);
    split_one(f0.z, &h[2], &l[2]);
    split_one(f0.w, &h[3], &l[3]);
    split_one(f1.x, &h[4], &l[4]);
    split_one(f1.y, &h[5], &l[5]);
    split_one(f1.z, &h[6], &l[6]);
    split_one(f1.w, &h[7], &l[7]);
    uint4 uh, ul;
    uh.x = pack2(h[0], h[1]); uh.y = pack2(h[2], h[3]);
    uh.z = pack2(h[4], h[5]); uh.w = pack2(h[6], h[7]);
    ul.x = pack2(l[0], l[1]); ul.y = pack2(l[2], l[3]);
    ul.z = pack2(l[4], l[5]); ul.w = pack2(l[6], l[7]);
    *(uint4*)dstH = uh;
    *(uint4*)dstL = ul;
}

template <int EPI>
__device__ __forceinline__ void gemm_core(const float* __restrict__ Af,
                                          const __nv_bfloat16* __restrict__ Bth,
                                          const __nv_bfloat16* __restrict__ Btl,
                                          const float* __restrict__ bias,
                                          float* __restrict__ out,
                                          int K, int N) {
    __shared__ __nv_bfloat16 AsH[2][BM * ASTR], AsL[2][BM * ASTR];
    __shared__ __nv_bfloat16 BsH[2][BN * BSTR], BsL[2][BN * BSTR];

    int tid  = threadIdx.x;
    int warp = tid >> 5, lane = tid & 31;
    int wm = warp >> 1, wn = warp & 1;   // 4 (m) x 2 (n) warps
    int gr = lane >> 2, tc = lane & 3;
    int m0 = blockIdx.x * BM, n0 = blockIdx.y * BN;

    float c[2][4][4];
#pragma unroll
    for (int a = 0; a < 2; a++)
#pragma unroll
        for (int b = 0; b < 4; b++)
#pragma unroll
            for (int q = 0; q < 4; q++) c[a][b][q] = 0.f;

    int arow = tid >> 1, ahalf = tid & 1;        // 128 rows x 2 halves of 8
    int brow = (tid & 127) >> 1, bhalf = tid & 1;
    const int KT = K >> 4;

    const float* aBase = Af + (size_t)(m0 + arow) * K + ahalf * 8;
    const __nv_bfloat16* bhBase = Bth + (size_t)(n0 + brow) * K + bhalf * 8;
    const __nv_bfloat16* blBase = Btl + (size_t)(n0 + brow) * K + bhalf * 8;
    int aSlot = arow * ASTR + ahalf * 8;
    int bSlot = brow * BSTR + bhalf * 8;

    // Prologue: tile 0 -> stage 0
    {
        const float4* pA = (const float4*)(aBase);
        float4 f0 = pA[0], f1 = pA[1];
        cvt_store_a(&AsH[0][aSlot], &AsL[0][aSlot], f0, f1);
        if (tid < 128) {
            *(uint4*)(&BsH[0][bSlot]) = *(const uint4*)(bhBase);
            *(uint4*)(&BsL[0][bSlot]) = *(const uint4*)(blBase);
        }
    }
    __syncthreads();

    for (int kt = 0; kt < KT; kt++) {
        int cur = kt & 1;
        int nk = kt + 1;
        bool have = nk < KT;

        // Prefetch next tile's globals into registers (overlaps with mmas below).
        float4 na0, na1;
        uint4 nbh, nbl;
        if (have) {
            const float4* pA = (const float4*)(aBase + (nk << 4));
            na0 = pA[0];
            na1 = pA[1];
            if (tid < 128) {
                nbh = *(const uint4*)(bhBase + (nk << 4));
                nbl = *(const uint4*)(blBase + (nk << 4));
            }
        }

        // Fragment loads from current stage.
        unsigned aH[2][4], aL[2][4], bH[4][2], bL[4][2];
#pragma unroll
        for (int mf = 0; mf < 2; mf++) {
            int r = wm * 32 + mf * 16 + gr;
            const __nv_bfloat16* pH = &AsH[cur][r * ASTR + tc * 2];
            const __nv_bfloat16* pL = &AsL[cur][r * ASTR + tc * 2];
            aH[mf][0] = *(const unsigned*)(pH);
            aH[mf][1] = *(const unsigned*)(pH + 8 * ASTR);
            aH[mf][2] = *(const unsigned*)(pH + 8);
            aH[mf][3] = *(const unsigned*)(pH + 8 * ASTR + 8);
            aL[mf][0] = *(const unsigned*)(pL);
            aL[mf][1] = *(const unsigned*)(pL + 8 * ASTR);
            aL[mf][2] = *(const unsigned*)(pL + 8);
            aL[mf][3] = *(const unsigned*)(pL + 8 * ASTR + 8);
        }
#pragma unroll
        for (int nf = 0; nf < 4; nf++) {
            int n = wn * 32 + nf * 8 + gr;
            const __nv_bfloat16* pH = &BsH[cur][n * BSTR + tc * 2];
            const __nv_bfloat16* pL = &BsL[cur][n * BSTR + tc * 2];
            bH[nf][0] = *(const unsigned*)(pH);
            bH[nf][1] = *(const unsigned*)(pH + 8);
            bL[nf][0] = *(const unsigned*)(pL);
            bL[nf][1] = *(const unsigned*)(pL + 8);
        }
#pragma unroll
        for (int mf = 0; mf < 2; mf++)
#pragma unroll
            for (int nf = 0; nf < 4; nf++) {
                mma16816(c[mf][nf], aH[mf], bH[nf]);  // hi*hi
                mma16816(c[mf][nf], aH[mf], bL[nf]);  // hi*lo
                mma16816(c[mf][nf], aL[mf], bH[nf]);  // lo*hi
            }

        // Store prefetched tile into the other stage.
        if (have) {
            int nxt = nk & 1;
            cvt_store_a(&AsH[nxt][aSlot], &AsL[nxt][aSlot], na0, na1);
            if (tid < 128) {
                *(uint4*)(&BsH[nxt][bSlot]) = nbh;
                *(uint4*)(&BsL[nxt][bSlot]) = nbl;
            }
        }
        __syncthreads();
    }

#pragma unroll
    for (int mf = 0; mf < 2; mf++) {
#pragma unroll
        for (int nf = 0; nf < 4; nf++) {
            int row0 = m0 + wm * 32 + mf * 16 + gr;
            int col0 = n0 + wn * 32 + nf * 8 + tc * 2;
#pragma unroll
            for (int h = 0; h < 2; h++) {
                int r = row0 + h * 8;
#pragma unroll
                for (int q = 0; q < 2; q++) {
                    int cc = col0 + q;
                    float v = c[mf][nf][h * 2 + q];
                    if (EPI == 1) v = fmaxf(v + bias[cc], 0.f);
                    out[(size_t)r * N + cc] = v;
                }
            }
        }
    }
}

__global__ void __launch_bounds__(256) kx_gemm1(const float* __restrict__ b1) {
    gemm_core<1>(gx_p1, gx_w1h, gx_w1l, b1, gx_h, DIN, HID);
}
__global__ void __launch_bounds__(256) kx_gemm2() {
    gemm_core<0>(gx_h, gx_w2h, gx_w2l, nullptr, gx_t, HID, DIN);
}

// ---------------------------------------------------------------------------
extern "C" void kernel_launch(void* const* d_in, const int* in_sizes, int n_in,
                              void* d_out, int out_size) {
    const float* A  = (const float*)d_in[0];
    const float* x  = (const float*)d_in[1];
    const float* W1 = (const float*)d_in[2];
    const float* b1 = (const float*)d_in[3];
    const float* W2 = (const float*)d_in[4];
    const float* b2 = (const float*)d_in[5];
    const float* sp = (const float*)d_in[6];
    float* out = (float*)d_out;

    kx_zero_cnt<<<32, 256>>>();                     // 0
    kx_extract<<<8192, 256>>>((const float4*)A);    // 1
    kx_dis<<<32, 256>>>();                          // 2
    kx_prop1<<<NN, 64>>>(x);                        // 3  <- profiled slot
    kx_tsplit_both<<<512, 256>>>(W1, W2);           // 4
    kx_gemm1<<<dim3(NN / BM, HID / BN), 256>>>(b1); // 5
    kx_gemm2<<<dim3(NN / BM, DIN / BN), 256>>>();   // 6
    kx_prop2epi<<<NN, 64>>>(x, b2, sp, out);        // 7
}